// round 1
// baseline (speedup 1.0000x reference)
#include <cuda_runtime.h>
#include <cuda_bf16.h>

#define BB 1024
#define TT 256
#define VV 256
#define HH 32

// hs scratch, layout [t][b][h]  (row r = t*B + b is contiguous 32 floats)
__device__ float g_hs[TT * BB * HH];

// ---------------------------------------------------------------------------
// fast tanh: tanh(x) = (e^{2x}-1)/(e^{2x}+1) via MUFU ex2 + fast divide
// ---------------------------------------------------------------------------
__device__ __forceinline__ float fast_tanh(float x) {
    x = fminf(fmaxf(x, -15.f), 15.f);
    float e = __expf(2.f * x);
    return __fdividef(e - 1.f, e + 1.f);
}

// ---------------------------------------------------------------------------
// Kernel A: embedding gather + recurrence.
// One warp per batch element. h[j] lives in lane j. W_hh column j in lane-j
// registers. W_xh (32KB) and this block's 8 token rows (8KB) staged in SMEM.
// ---------------------------------------------------------------------------
__global__ void __launch_bounds__(256)
rnn_recurrence(const int* __restrict__ X, const float* __restrict__ Wxh,
               const float* __restrict__ Whh, const float* __restrict__ bh)
{
    __shared__ float sWxh[VV * HH];   // 32 KB
    __shared__ int   sX[8][TT];       // 8 KB

    const int tid  = threadIdx.x;
    const int lane = tid & 31;
    const int warp = tid >> 5;
    const int b    = blockIdx.x * 8 + warp;

    // stage W_xh
    {
        const float4* s = (const float4*)Wxh;
        float4*       d = (float4*)sWxh;
        #pragma unroll
        for (int i = tid; i < (VV * HH) / 4; i += 256) d[i] = s[i];
    }
    // stage this block's 8 token rows
    {
        const int4* s = (const int4*)(X + (long)blockIdx.x * 8 * TT);
        int4*       d = (int4*)&sX[0][0];
        #pragma unroll
        for (int i = tid; i < (8 * TT) / 4; i += 256) d[i] = s[i];
    }

    // W_hh column `lane` into registers: w[i] = Whh[i][lane]
    float w[HH];
    #pragma unroll
    for (int i = 0; i < HH; i++) w[i] = Whh[i * HH + lane];
    const float bhv = bh[lane];

    __syncthreads();

    float  h    = 0.f;
    float* outp = g_hs + (long)b * HH + lane;

    int   tok = sX[warp][0];
    float xe  = sWxh[tok * HH + lane];

    #pragma unroll 2
    for (int t = 0; t < TT; t++) {
        const int tokn = sX[warp][(t + 1) & (TT - 1)];  // prefetch next token

        // new_h[lane] = sum_i h[i] * Whh[i][lane], 4 accumulators
        float a0 = 0.f, a1 = 0.f, a2 = 0.f, a3 = 0.f;
        #pragma unroll
        for (int i = 0; i < HH; i += 4) {
            a0 = fmaf(__shfl_sync(0xffffffffu, h, i + 0), w[i + 0], a0);
            a1 = fmaf(__shfl_sync(0xffffffffu, h, i + 1), w[i + 1], a1);
            a2 = fmaf(__shfl_sync(0xffffffffu, h, i + 2), w[i + 2], a2);
            a3 = fmaf(__shfl_sync(0xffffffffu, h, i + 3), w[i + 3], a3);
        }
        float s = (xe + bhv) + ((a0 + a1) + (a2 + a3));

        // prefetch next embedding while tanh chain runs
        xe = sWxh[tokn * HH + lane];

        h = fast_tanh(s);
        outp[(long)t * (BB * HH)] = h;   // coalesced 128B per warp
    }
}

// ---------------------------------------------------------------------------
// packed f32x2 helpers (sm_100+: fma.rn.f32x2 — 2x fp32 throughput vs FFMA)
// ---------------------------------------------------------------------------
__device__ __forceinline__ unsigned long long splat2(float x) {
    unsigned long long r;
    asm("mov.b64 %0, {%1, %1};" : "=l"(r) : "f"(x));
    return r;
}
__device__ __forceinline__ unsigned long long fma2(unsigned long long a,
                                                   unsigned long long b,
                                                   unsigned long long c) {
    unsigned long long d;
    asm("fma.rn.f32x2 %0, %1, %2, %3;" : "=l"(d) : "l"(a), "l"(b), "l"(c));
    return d;
}

// ---------------------------------------------------------------------------
// Kernel B: logits[b][t][v] = sum_h hs[t][b][h] * Whq[h][v] + bq[v]
// 256 threads / 8 warps per block; 4 rows per warp (32 rows/block).
// Each lane owns 4 v-pairs (v = 2*(lane+32j), +1). W_hq rows read from SMEM
// as float2; h broadcast per-i via SHFL; accumulate with fma.rn.f32x2.
// ---------------------------------------------------------------------------
__global__ void __launch_bounds__(256)
rnn_logits(const float* __restrict__ Whq, const float* __restrict__ bq,
           float* __restrict__ out)
{
    __shared__ float sW[HH * VV];   // 32 KB, [h][v]
    __shared__ float sbq[VV];       // 1 KB

    const int tid  = threadIdx.x;
    const int lane = tid & 31;
    const int warp = tid >> 5;

    {
        const float4* s = (const float4*)Whq;
        float4*       d = (float4*)sW;
        #pragma unroll
        for (int i = tid; i < (HH * VV) / 4; i += 256) d[i] = s[i];
        if (tid < VV / 4) ((float4*)sbq)[tid] = ((const float4*)bq)[tid];
    }
    __syncthreads();

    const long row0 = (long)blockIdx.x * 32 + warp * 4;

    // h for 4 rows: lane holds h[lane] of each row
    float hr0 = g_hs[(row0 + 0) * HH + lane];
    float hr1 = g_hs[(row0 + 1) * HH + lane];
    float hr2 = g_hs[(row0 + 2) * HH + lane];
    float hr3 = g_hs[(row0 + 3) * HH + lane];

    const unsigned long long* sW2 = (const unsigned long long*)sW;  // 128 pairs / h-row

    unsigned long long acc[4][4];
    #pragma unroll
    for (int r = 0; r < 4; r++)
        #pragma unroll
        for (int j = 0; j < 4; j++) acc[r][j] = 0ull;

    #pragma unroll
    for (int i = 0; i < HH; i++) {
        const unsigned long long w0 = sW2[i * 128 + lane];
        const unsigned long long w1 = sW2[i * 128 + lane + 32];
        const unsigned long long w2 = sW2[i * 128 + lane + 64];
        const unsigned long long w3 = sW2[i * 128 + lane + 96];

        const unsigned long long h0 = splat2(__shfl_sync(0xffffffffu, hr0, i));
        const unsigned long long h1 = splat2(__shfl_sync(0xffffffffu, hr1, i));
        const unsigned long long h2 = splat2(__shfl_sync(0xffffffffu, hr2, i));
        const unsigned long long h3 = splat2(__shfl_sync(0xffffffffu, hr3, i));

        acc[0][0] = fma2(h0, w0, acc[0][0]);
        acc[0][1] = fma2(h0, w1, acc[0][1]);
        acc[0][2] = fma2(h0, w2, acc[0][2]);
        acc[0][3] = fma2(h0, w3, acc[0][3]);
        acc[1][0] = fma2(h1, w0, acc[1][0]);
        acc[1][1] = fma2(h1, w1, acc[1][1]);
        acc[1][2] = fma2(h1, w2, acc[1][2]);
        acc[1][3] = fma2(h1, w3, acc[1][3]);
        acc[2][0] = fma2(h2, w0, acc[2][0]);
        acc[2][1] = fma2(h2, w1, acc[2][1]);
        acc[2][2] = fma2(h2, w2, acc[2][2]);
        acc[2][3] = fma2(h2, w3, acc[2][3]);
        acc[3][0] = fma2(h3, w0, acc[3][0]);
        acc[3][1] = fma2(h3, w1, acc[3][1]);
        acc[3][2] = fma2(h3, w2, acc[3][2]);
        acc[3][3] = fma2(h3, w3, acc[3][3]);
    }

    const float2* sbq2 = (const float2*)sbq;
    #pragma unroll
    for (int r = 0; r < 4; r++) {
        const long row = row0 + r;          // row = t*B + b
        const int  t   = (int)(row >> 10);  // B = 1024
        const int  b   = (int)(row & 1023);
        float2* o = (float2*)(out + (((long)b * TT + t) * VV));
        #pragma unroll
        for (int j = 0; j < 4; j++) {
            union { unsigned long long u; float2 f; } cv;
            cv.u = acc[r][j];
            const float2 q = sbq2[lane + 32 * j];
            cv.f.x += q.x;
            cv.f.y += q.y;
            o[lane + 32 * j] = cv.f;        // coalesced 256B per j per warp
        }
    }
}

// ---------------------------------------------------------------------------
// kernel_launch
// inputs: 0:X int32[B,T]  1:W_xh f32[V,H]  2:W_hh f32[H,H]  3:b_h f32[H]
//         4:W_hq f32[H,V] 5:b_q f32[V]     out: f32[B,T,V]
// ---------------------------------------------------------------------------
extern "C" void kernel_launch(void* const* d_in, const int* in_sizes, int n_in,
                              void* d_out, int out_size)
{
    const int*   X   = (const int*)d_in[0];
    const float* Wxh = (const float*)d_in[1];
    const float* Whh = (const float*)d_in[2];
    const float* bh  = (const float*)d_in[3];
    const float* Whq = (const float*)d_in[4];
    const float* bq  = (const float*)d_in[5];
    float*       out = (float*)d_out;

    rnn_recurrence<<<BB / 8, 256>>>(X, Wxh, Whh, bh);
    rnn_logits<<<(TT * BB) / 32, 256>>>(Whq, bq, out);
}